// round 1
// baseline (speedup 1.0000x reference)
#include <cuda_runtime.h>
#include <math.h>

// ---------------- problem constants ----------------
#define BB   64      // batch
#define CIN  64      // input channels
#define T0   4096
#define HH   64      // h/2
#define H    128     // h
#define T1   2048
#define T2   1024
#define RH   64
#define DD   64      // embedding dim
#define KCB  512     // codebook size
#define NN   (BB * T2)   // 65536 vectors

// ---------------- scratch (device globals; no allocation allowed) ----------------
__device__ float g_h1[(size_t)BB * HH * T1];   // after conv1
__device__ float g_h2[(size_t)BB * H  * T2];   // after conv2
__device__ float g_h3[(size_t)BB * H  * T2];   // running h (conv3 + residuals)
__device__ float g_ta[(size_t)BB * RH * T2];   // residual mid tensor
__device__ float g_Wc[DD * H];                 // fused wpq @ w_out
__device__ float g_bc[DD];                     // fused bias
__device__ float g_cnorm[KCB];                 // ||codebook_k||^2
__device__ int   g_hist[KCB];
__device__ float g_losssum;

// ---------------- small precompute: Wc, bc, codebook norms ----------------
__global__ void precompute_k(const float* __restrict__ wpq, const float* __restrict__ w_out,
                             const float* __restrict__ b_out, const float* __restrict__ bpq,
                             const float* __restrict__ cb)
{
    int tid = threadIdx.x;
    for (int i = tid; i < DD * H; i += 256) {
        int dq = i / H, ch = i % H;
        float s = 0.f;
        #pragma unroll
        for (int d = 0; d < DD; d++) s = fmaf(wpq[dq * DD + d], w_out[d * H + ch], s);
        g_Wc[i] = s;
    }
    for (int dq = tid; dq < DD; dq += 256) {
        float s = bpq[dq];
        #pragma unroll
        for (int d = 0; d < DD; d++) s = fmaf(wpq[dq * DD + d], b_out[d], s);
        g_bc[dq] = s;
    }
    for (int k = tid; k < KCB; k += 256) {
        float s = 0.f;
        #pragma unroll
        for (int d = 0; d < DD; d++) { float c = cb[k * DD + d]; s = fmaf(c, c, s); }
        g_cnorm[k] = s;
    }
}

__global__ void zero_small_k()
{
    int i = blockIdx.x * blockDim.x + threadIdx.x;
    if (i < KCB) g_hist[i] = 0;
    if (i == 0)  g_losssum = 0.f;
}

// zero the one-hot encodings region (8-byte aligned; float2 stores)
__global__ void zero_enc_k(float* __restrict__ enc)
{
    size_t total = (size_t)NN * KCB / 2;
    float2* p = (float2*)enc;
    for (size_t i = (size_t)blockIdx.x * blockDim.x + threadIdx.x; i < total;
         i += (size_t)gridDim.x * blockDim.x)
        p[i] = make_float2(0.f, 0.f);
}

// ---------------- direct conv1d (K in {3,4}), 4 output channels/thread ----------------
template<int KW, int STRIDE, bool RELU_IN, bool RELU_OUT, bool HAS_BIAS>
__global__ void __launch_bounds__(128) conv_k(
    const float* __restrict__ in, const float* __restrict__ w,
    const float* __restrict__ bias, float* __restrict__ out,
    int Cin, int Tin, int Cout, int Tout)
{
    __shared__ float sw[2048];  // 4 output channels x Cin x KW (max 4*128*4)

    const int t   = blockIdx.x * 128 + threadIdx.x;
    const int co0 = blockIdx.y * 4;
    const int b   = blockIdx.z;

    // stage this block's weight slice in SMEM
    const int wcnt = 4 * Cin * KW;
    const float* wbase = w + (size_t)co0 * Cin * KW;
    for (int i = threadIdx.x; i < wcnt; i += 128) sw[i] = wbase[i];
    __syncthreads();

    const float* inb = in + (size_t)b * Cin * Tin;
    const int tin0 = t * STRIDE - 1;   // pad = 1 in all K>1 convs here

    float acc[4];
    #pragma unroll
    for (int j = 0; j < 4; j++) acc[j] = HAS_BIAS ? bias[co0 + j] : 0.f;

    const bool interior = (tin0 >= 0) && (tin0 + KW <= Tin);
    if (interior) {
        for (int ci = 0; ci < Cin; ci++) {
            float xv[KW];
            const float* xp = inb + (size_t)ci * Tin + tin0;
            #pragma unroll
            for (int k = 0; k < KW; k++) {
                float v = xp[k];
                xv[k] = RELU_IN ? fmaxf(v, 0.f) : v;
            }
            #pragma unroll
            for (int j = 0; j < 4; j++) {
                #pragma unroll
                for (int k = 0; k < KW; k++)
                    acc[j] = fmaf(xv[k], sw[j * Cin * KW + ci * KW + k], acc[j]);
            }
        }
    } else {
        for (int ci = 0; ci < Cin; ci++) {
            float xv[KW];
            #pragma unroll
            for (int k = 0; k < KW; k++) {
                int p = tin0 + k;
                float v = (p >= 0 && p < Tin) ? inb[(size_t)ci * Tin + p] : 0.f;
                xv[k] = RELU_IN ? fmaxf(v, 0.f) : v;
            }
            #pragma unroll
            for (int j = 0; j < 4; j++) {
                #pragma unroll
                for (int k = 0; k < KW; k++)
                    acc[j] = fmaf(xv[k], sw[j * Cin * KW + ci * KW + k], acc[j]);
            }
        }
    }

    #pragma unroll
    for (int j = 0; j < 4; j++) {
        float v = acc[j];
        if (RELU_OUT) v = fmaxf(v, 0.f);
        out[(size_t)b * Cout * Tout + (size_t)(co0 + j) * Tout + t] = v;
    }
}

// ---------------- 1x1 conv (residual projection), optional accumulate ----------------
template<bool ACC>
__global__ void __launch_bounds__(128) conv1x1_k(
    const float* __restrict__ in, const float* __restrict__ w,
    float* __restrict__ out, int Cin, int Cout, int T)
{
    __shared__ float sw[512];  // 4 x Cin (Cin <= 128)
    const int t   = blockIdx.x * 128 + threadIdx.x;
    const int co0 = blockIdx.y * 4;
    const int b   = blockIdx.z;

    for (int i = threadIdx.x; i < 4 * Cin; i += 128) sw[i] = w[(size_t)co0 * Cin + i];
    __syncthreads();

    float a[4] = {0.f, 0.f, 0.f, 0.f};
    const float* inb = in + (size_t)b * Cin * T + t;
    for (int ci = 0; ci < Cin; ci++) {
        float xv = inb[(size_t)ci * T];
        #pragma unroll
        for (int j = 0; j < 4; j++) a[j] = fmaf(xv, sw[j * Cin + ci], a[j]);
    }
    #pragma unroll
    for (int j = 0; j < 4; j++) {
        size_t o = (size_t)b * Cout * T + (size_t)(co0 + j) * T + t;
        if (ACC) out[o] += a[j]; else out[o] = a[j];
    }
}

// ---------------- fused relu + (wpq@w_out) 1x1 + transpose -> z_e (B,T,D) ----------------
__global__ void __launch_bounds__(128) z_k(const float* __restrict__ h, float* __restrict__ ze)
{
    __shared__ float sw[4 * H];
    __shared__ float sb[4];
    const int t   = blockIdx.x * 128 + threadIdx.x;
    const int dq0 = blockIdx.y * 4;
    const int b   = blockIdx.z;

    for (int i = threadIdx.x; i < 4 * H; i += 128) sw[i] = g_Wc[dq0 * H + i];
    if (threadIdx.x < 4) sb[threadIdx.x] = g_bc[dq0 + threadIdx.x];
    __syncthreads();

    float a[4];
    #pragma unroll
    for (int j = 0; j < 4; j++) a[j] = sb[j];

    const float* hb = h + (size_t)b * H * T2 + t;
    for (int ch = 0; ch < H; ch++) {
        float xv = fmaxf(hb[(size_t)ch * T2], 0.f);
        #pragma unroll
        for (int j = 0; j < 4; j++) a[j] = fmaf(xv, sw[j * H + ch], a[j]);
    }
    const size_t n = (size_t)b * T2 + t;
    #pragma unroll
    for (int j = 0; j < 4; j++) ze[n * DD + dq0 + j] = a[j];
}

// ---------------- vector quantization: codebook fully in SMEM ----------------
__global__ void __launch_bounds__(256) vq_k(const float* __restrict__ ze,
                                            const float* __restrict__ cb,
                                            float* __restrict__ zq,
                                            float* __restrict__ enc,
                                            float* __restrict__ idxout)
{
    extern __shared__ float s[];
    float* scb = s;               // KCB * DD
    float* scn = s + KCB * DD;    // KCB

    for (int i = threadIdx.x; i < KCB * DD; i += 256) scb[i] = cb[i];
    for (int i = threadIdx.x; i < KCB; i += 256)      scn[i] = g_cnorm[i];
    __syncthreads();

    const int n = blockIdx.x * 256 + threadIdx.x;
    float f[DD];
    #pragma unroll
    for (int d = 0; d < DD; d++) f[d] = ze[(size_t)n * DD + d];

    float best = 3.4e38f;
    int bestk = 0;
    const float4* scb4 = (const float4*)scb;
    #pragma unroll 1
    for (int k = 0; k < KCB; k++) {
        float dot = 0.f;
        #pragma unroll
        for (int q = 0; q < DD / 4; q++) {
            float4 c = scb4[k * (DD / 4) + q];
            dot = fmaf(f[4 * q + 0], c.x, dot);
            dot = fmaf(f[4 * q + 1], c.y, dot);
            dot = fmaf(f[4 * q + 2], c.z, dot);
            dot = fmaf(f[4 * q + 3], c.w, dot);
        }
        float dist = scn[k] - 2.f * dot;   // + ||f||^2 is constant -> same argmin
        if (dist < best) { best = dist; bestk = k; }
    }

    float sq = 0.f;
    #pragma unroll
    for (int d = 0; d < DD; d++) {
        float c = scb[bestk * DD + d];
        zq[(size_t)n * DD + d] = c;        // z_q_st == z_q in forward pass
        float df = c - f[d];
        sq = fmaf(df, df, sq);
    }
    enc[(size_t)n * KCB + bestk] = 1.f;
    idxout[n] = (float)bestk;
    atomicAdd(&g_hist[bestk], 1);

    // reduce sq within block, one atomic per block
    #pragma unroll
    for (int o = 16; o > 0; o >>= 1) sq += __shfl_down_sync(0xffffffffu, sq, o);
    __shared__ float wsum[8];
    if ((threadIdx.x & 31) == 0) wsum[threadIdx.x >> 5] = sq;
    __syncthreads();
    if (threadIdx.x < 8) {
        float v = wsum[threadIdx.x];
        #pragma unroll
        for (int o = 4; o > 0; o >>= 1) v += __shfl_down_sync(0xffu, v, o);
        if (threadIdx.x == 0) atomicAdd(&g_losssum, v);
    }
}

// ---------------- finalize scalars: loss + perplexity ----------------
__global__ void fin_k(float* __restrict__ loss_out, float* __restrict__ perp_out)
{
    __shared__ float red[512];
    const int k = threadIdx.x;
    float p = (float)g_hist[k] * (1.0f / (float)NN);
    red[k] = p * logf(p + 1e-10f);
    __syncthreads();
    for (int s2 = 256; s2 > 0; s2 >>= 1) {
        if (k < s2) red[k] += red[k + s2];
        __syncthreads();
    }
    if (k == 0) {
        perp_out[0] = expf(-red[0]);
        loss_out[0] = 1.25f * g_losssum / (float)((size_t)NN * DD);  // (1+BETA)*MSE
    }
}

// ---------------- launcher ----------------
extern "C" void kernel_launch(void* const* d_in, const int* in_sizes, int n_in,
                              void* d_out, int out_size)
{
    const float* x     = (const float*)d_in[0];
    const float* w1    = (const float*)d_in[1];
    const float* b1    = (const float*)d_in[2];
    const float* w2    = (const float*)d_in[3];
    const float* b2    = (const float*)d_in[4];
    const float* w3    = (const float*)d_in[5];
    const float* b3    = (const float*)d_in[6];
    const float* r0w1  = (const float*)d_in[7];
    const float* r0w2  = (const float*)d_in[8];
    const float* r1w1  = (const float*)d_in[9];
    const float* r1w2  = (const float*)d_in[10];
    const float* w_out = (const float*)d_in[11];
    const float* b_out = (const float*)d_in[12];
    const float* wpq   = (const float*)d_in[13];
    const float* bpq   = (const float*)d_in[14];
    const float* cb    = (const float*)d_in[15];

    float* outp = (float*)d_out;
    const size_t NZ = (size_t)NN * DD;                 // 4,194,304
    float* o_loss = outp;                              // [1]
    float* o_zq   = outp + 1;                          // [NZ]
    float* o_perp = outp + 1 + NZ;                     // [1]
    float* o_ze   = outp + 2 + NZ;                     // [NZ]
    float* o_enc  = outp + 2 + 2 * NZ;                 // [NN*KCB]
    float* o_idx  = outp + 2 + 2 * NZ + (size_t)NN * KCB;  // [NN]

    // scalars / fused weights / output-region zeroing (independent of conv chain)
    precompute_k<<<1, 256>>>(wpq, w_out, b_out, bpq, cb);
    zero_small_k<<<2, 256>>>();
    zero_enc_k<<<8192, 256>>>(o_enc);

    // encoder conv stack
    conv_k<4, 2, false, true,  true ><<<dim3(T1 / 128, HH / 4, BB), 128>>>(x,    w1, b1, g_h1, CIN, T0, HH, T1);
    conv_k<4, 2, false, true,  true ><<<dim3(T2 / 128, H  / 4, BB), 128>>>(g_h1, w2, b2, g_h2, HH,  T1, H,  T2);
    conv_k<3, 1, false, false, true ><<<dim3(T2 / 128, H  / 4, BB), 128>>>(g_h2, w3, b3, g_h3, H,   T2, H,  T2);
    // residual block 0
    conv_k<3, 1, true,  true,  false><<<dim3(T2 / 128, RH / 4, BB), 128>>>(g_h3, r0w1, nullptr, g_ta, H, T2, RH, T2);
    conv1x1_k<true><<<dim3(T2 / 128, H / 4, BB), 128>>>(g_ta, r0w2, g_h3, RH, H, T2);
    // residual block 1
    conv_k<3, 1, true,  true,  false><<<dim3(T2 / 128, RH / 4, BB), 128>>>(g_h3, r1w1, nullptr, g_ta, H, T2, RH, T2);
    conv1x1_k<true><<<dim3(T2 / 128, H / 4, BB), 128>>>(g_ta, r1w2, g_h3, RH, H, T2);

    // fused relu + w_out + wpq (1x1 o 1x1 == single 64x128 matrix) -> z_e (B,T,D)
    z_k<<<dim3(T2 / 128, DD / 4, BB), 128>>>(g_h3, o_ze);

    // vector quantization (codebook + norms resident in SMEM)
    const int vq_smem = (KCB * DD + KCB) * (int)sizeof(float);  // 133,120 B
    cudaFuncSetAttribute(vq_k, cudaFuncAttributeMaxDynamicSharedMemorySize, vq_smem);
    vq_k<<<NN / 256, 256, vq_smem>>>(o_ze, cb, o_zq, o_enc, o_idx);

    fin_k<<<1, 512>>>(o_loss, o_perp);
}

// round 3
// speedup vs baseline: 3.9222x; 3.9222x over previous
#include <cuda_runtime.h>
#include <math.h>

// ---------------- problem constants ----------------
#define BB   64
#define CIN  64
#define T0   4096
#define HH   64
#define H    128
#define T1   2048
#define T2   1024
#define RH   64
#define DD   64
#define KCB  512
#define NN   (BB * T2)

// ---------------- scratch ----------------
__device__ float g_h1[(size_t)BB * HH * T1];
__device__ float g_h2[(size_t)BB * H  * T2];
__device__ float g_h3[(size_t)BB * H  * T2];
__device__ float g_WcT[H * DD];     // fused (wpq @ w_out), transposed [ch][dq]
__device__ float g_bc[DD];
__device__ float g_cnorm[KCB];
__device__ int   g_hist[KCB];
__device__ float g_losssum;

// ---------------- precompute: WcT, bc, codebook norms, zero scalars ----------------
__global__ void precompute_k(const float* __restrict__ wpq, const float* __restrict__ w_out,
                             const float* __restrict__ b_out, const float* __restrict__ bpq,
                             const float* __restrict__ cb)
{
    int tid = threadIdx.x;
    for (int i = tid; i < DD * H; i += 256) {
        int dq = i >> 7, ch = i & 127;
        float s = 0.f;
        #pragma unroll
        for (int d = 0; d < DD; d++) s = fmaf(wpq[dq * DD + d], w_out[d * H + ch], s);
        g_WcT[ch * DD + dq] = s;
    }
    for (int dq = tid; dq < DD; dq += 256) {
        float s = bpq[dq];
        #pragma unroll
        for (int d = 0; d < DD; d++) s = fmaf(wpq[dq * DD + d], b_out[d], s);
        g_bc[dq] = s;
    }
    for (int k = tid; k < KCB; k += 256) {
        float s = 0.f;
        #pragma unroll
        for (int d = 0; d < DD; d++) { float c = cb[k * DD + d]; s = fmaf(c, c, s); }
        g_cnorm[k] = s;
        g_hist[k] = 0;
    }
    if (tid == 0) g_losssum = 0.f;
}

// zero the one-hot encodings region (region is 8-byte aligned -> float2)
__global__ void zero_enc_k(float* __restrict__ enc)
{
    size_t total = (size_t)NN * KCB / 2;
    float2* p = (float2*)enc;
    for (size_t i = (size_t)blockIdx.x * blockDim.x + threadIdx.x; i < total;
         i += (size_t)gridDim.x * blockDim.x)
        p[i] = make_float2(0.f, 0.f);
}

// ---------------- K=4 stride=2 pad=1 conv, bias + relu out ----------------
// block: 128 threads; thread = 2 co x 8 t. co-tile 16, t-tile 128.
__global__ void __launch_bounds__(128) convS2_k(
    const float* __restrict__ in, const float* __restrict__ w,
    const float* __restrict__ bias, float* __restrict__ out,
    int Cin, int Tin, int Cout, int Tout)
{
    __shared__ float sx[16 * 258];   // 16 ci x 258 in-span
    __shared__ float swt[16 * 65];   // 16 co x (16 ci * 4 k), pitch 65

    const int tid = threadIdx.x;
    const int cs  = tid & 7;         // co slot (2 co each)
    const int ts  = tid >> 3;        // t slot (8 t each)
    const int t0  = blockIdx.x * 128;
    const int co0 = blockIdx.y * 16;
    const int b   = blockIdx.z;

    float acc[2][8];
    #pragma unroll
    for (int c = 0; c < 2; c++) {
        float bv = bias[co0 + cs * 2 + c];
        #pragma unroll
        for (int j = 0; j < 8; j++) acc[c][j] = bv;
    }

    for (int cc = 0; cc < Cin; cc += 16) {
        for (int idx = tid; idx < 16 * 258; idx += 128) {
            int ci = idx / 258, p = idx - ci * 258;
            int g = 2 * t0 - 1 + p;
            sx[idx] = (g >= 0 && g < Tin) ? in[((size_t)b * Cin + cc + ci) * Tin + g] : 0.f;
        }
        for (int idx = tid; idx < 16 * 64; idx += 128) {
            int co = idx >> 6, r = idx & 63;
            swt[co * 65 + r] = w[(size_t)(co0 + co) * Cin * 4 + cc * 4 + r];
        }
        __syncthreads();

        #pragma unroll 4
        for (int ci = 0; ci < 16; ci++) {
            float x[18];
            #pragma unroll
            for (int p = 0; p < 18; p++) x[p] = sx[ci * 258 + ts * 16 + p];
            #pragma unroll
            for (int c = 0; c < 2; c++) {
                float wv[4];
                #pragma unroll
                for (int k = 0; k < 4; k++) wv[k] = swt[(cs * 2 + c) * 65 + ci * 4 + k];
                #pragma unroll
                for (int j = 0; j < 8; j++)
                    #pragma unroll
                    for (int k = 0; k < 4; k++)
                        acc[c][j] = fmaf(x[2 * j + k], wv[k], acc[c][j]);
            }
        }
        __syncthreads();
    }

    #pragma unroll
    for (int c = 0; c < 2; c++) {
        float4 v0 = make_float4(fmaxf(acc[c][0], 0.f), fmaxf(acc[c][1], 0.f),
                                fmaxf(acc[c][2], 0.f), fmaxf(acc[c][3], 0.f));
        float4 v1 = make_float4(fmaxf(acc[c][4], 0.f), fmaxf(acc[c][5], 0.f),
                                fmaxf(acc[c][6], 0.f), fmaxf(acc[c][7], 0.f));
        float4* op = (float4*)(out + ((size_t)b * Cout + co0 + cs * 2 + c) * Tout + t0 + ts * 8);
        op[0] = v0; op[1] = v1;
    }
}

// ---------------- K=3 stride=1 pad=1 conv, bias, no relu (conv3) ----------------
__global__ void __launch_bounds__(128) convS1_k(
    const float* __restrict__ in, const float* __restrict__ w,
    const float* __restrict__ bias, float* __restrict__ out,
    int Cin, int Cout)
{
    __shared__ float sx[32 * 130];
    __shared__ float swt[16 * 97];   // 16 co x (32 ci * 3 k), pitch 97

    const int tid = threadIdx.x;
    const int cs  = tid & 7;
    const int ts  = tid >> 3;
    const int t0  = blockIdx.x * 128;
    const int co0 = blockIdx.y * 16;
    const int b   = blockIdx.z;

    float acc[2][8];
    #pragma unroll
    for (int c = 0; c < 2; c++) {
        float bv = bias[co0 + cs * 2 + c];
        #pragma unroll
        for (int j = 0; j < 8; j++) acc[c][j] = bv;
    }

    for (int cc = 0; cc < Cin; cc += 32) {
        for (int idx = tid; idx < 32 * 130; idx += 128) {
            int ci = idx / 130, p = idx - ci * 130;
            int g = t0 - 1 + p;
            sx[idx] = (g >= 0 && g < T2) ? in[((size_t)b * Cin + cc + ci) * T2 + g] : 0.f;
        }
        for (int idx = tid; idx < 16 * 96; idx += 128) {
            int co = idx / 96, r = idx - co * 96;
            swt[co * 97 + r] = w[(size_t)(co0 + co) * Cin * 3 + cc * 3 + r];
        }
        __syncthreads();

        #pragma unroll 4
        for (int ci = 0; ci < 32; ci++) {
            float x[10];
            #pragma unroll
            for (int p = 0; p < 10; p++) x[p] = sx[ci * 130 + ts * 8 + p];
            #pragma unroll
            for (int c = 0; c < 2; c++) {
                float wv[3];
                #pragma unroll
                for (int k = 0; k < 3; k++) wv[k] = swt[(cs * 2 + c) * 97 + ci * 3 + k];
                #pragma unroll
                for (int j = 0; j < 8; j++)
                    #pragma unroll
                    for (int k = 0; k < 3; k++)
                        acc[c][j] = fmaf(x[j + k], wv[k], acc[c][j]);
            }
        }
        __syncthreads();
    }

    #pragma unroll
    for (int c = 0; c < 2; c++) {
        float4 v0 = make_float4(acc[c][0], acc[c][1], acc[c][2], acc[c][3]);
        float4 v1 = make_float4(acc[c][4], acc[c][5], acc[c][6], acc[c][7]);
        float4* op = (float4*)(out + ((size_t)b * Cout + co0 + cs * 2 + c) * T2 + t0 + ts * 8);
        op[0] = v0; op[1] = v1;
    }
}

// ---------------- fused residual block: out = h + W_b @ relu(conv3(relu(h), W_a)) ----------------
// 256 threads, t-tile 128. Intermediate (64 x 128) lives in smem.
#define RSH  (128 * 130)
#define RSTA (64 * 129)
#define RSW  (32 * 385)
__global__ void __launch_bounds__(256) resblock_k(
    const float* __restrict__ in, const float* __restrict__ wa,
    const float* __restrict__ wb, float* __restrict__ out)
{
    extern __shared__ float s[];
    float* sh  = s;            // raw h tile [128 ci][130]
    float* sta = s + RSH;      // relu'd mid tile [64][129]
    float* sw  = sta + RSTA;   // weights (wa chunk / wb)

    const int tid = threadIdx.x;
    const int t0  = blockIdx.x * 128;
    const int b   = blockIdx.z;

    for (int idx = tid; idx < RSH; idx += 256) {
        int ci = idx / 130, p = idx - ci * 130;
        int g = t0 - 1 + p;
        sh[idx] = (g >= 0 && g < T2) ? in[((size_t)b * H + ci) * T2 + g] : 0.f;
    }
    __syncthreads();

    // phase B: mid = relu(conv3(relu(h)))  — thread = 2 mid x 8 t
    {
        const int mslot = tid & 15;   // 16 mid-slots (2 mid each) per 32-chunk
        const int tslot = tid >> 4;   // 16 t-slots
        for (int mc = 0; mc < RH; mc += 32) {
            for (int idx = tid; idx < 32 * 384; idx += 256) {
                int m = idx / 384, r = idx - m * 384;
                sw[m * 385 + r] = wa[(size_t)(mc + m) * 384 + r];
            }
            __syncthreads();

            float acc[2][8];
            #pragma unroll
            for (int c = 0; c < 2; c++)
                #pragma unroll
                for (int j = 0; j < 8; j++) acc[c][j] = 0.f;

            #pragma unroll 2
            for (int ci = 0; ci < H; ci++) {
                float x[10];
                #pragma unroll
                for (int p = 0; p < 10; p++) x[p] = fmaxf(sh[ci * 130 + tslot * 8 + p], 0.f);
                #pragma unroll
                for (int c = 0; c < 2; c++) {
                    float wv[3];
                    #pragma unroll
                    for (int k = 0; k < 3; k++) wv[k] = sw[(2 * mslot + c) * 385 + ci * 3 + k];
                    #pragma unroll
                    for (int j = 0; j < 8; j++)
                        #pragma unroll
                        for (int k = 0; k < 3; k++)
                            acc[c][j] = fmaf(x[j + k], wv[k], acc[c][j]);
                }
            }
            #pragma unroll
            for (int c = 0; c < 2; c++)
                #pragma unroll
                for (int j = 0; j < 8; j++)
                    sta[(mc + 2 * mslot + c) * 129 + tslot * 8 + j] = fmaxf(acc[c][j], 0.f);
            __syncthreads();
        }
    }

    // phase C: out = h + wb @ mid  — thread = 8 co x 8 t
    {
        for (int idx = tid; idx < H * RH; idx += 256) {
            int co = idx >> 6, mid = idx & 63;
            sw[mid * 129 + co] = wb[idx];       // wb global layout [co][mid]
        }
        __syncthreads();

        const int coslot = tid & 15;   // co = coslot + 16*c
        const int tslot  = tid >> 4;
        float acc[8][8];
        #pragma unroll
        for (int c = 0; c < 8; c++)
            #pragma unroll
            for (int j = 0; j < 8; j++)
                acc[c][j] = sh[(coslot + 16 * c) * 130 + tslot * 8 + j + 1];

        #pragma unroll 2
        for (int mid = 0; mid < RH; mid++) {
            float xv[8], wv[8];
            #pragma unroll
            for (int j = 0; j < 8; j++) xv[j] = sta[mid * 129 + tslot * 8 + j];
            #pragma unroll
            for (int c = 0; c < 8; c++) wv[c] = sw[mid * 129 + coslot + 16 * c];
            #pragma unroll
            for (int c = 0; c < 8; c++)
                #pragma unroll
                for (int j = 0; j < 8; j++)
                    acc[c][j] = fmaf(xv[j], wv[c], acc[c][j]);
        }

        #pragma unroll
        for (int c = 0; c < 8; c++) {
            float4 v0 = make_float4(acc[c][0], acc[c][1], acc[c][2], acc[c][3]);
            float4 v1 = make_float4(acc[c][4], acc[c][5], acc[c][6], acc[c][7]);
            float4* op = (float4*)(out + ((size_t)b * H + coslot + 16 * c) * T2 + t0 + tslot * 8);
            op[0] = v0; op[1] = v1;
        }
    }
}

// ---------------- fused relu + (wpq o w_out) + transpose -> z_e (B,T,D) ----------------
// NOTE: z_e output region is only 8-byte aligned (base +2 floats) -> float2 stores.
#define ZSH (128 * 129)
#define ZSW (128 * 65)
__global__ void __launch_bounds__(128) zfused_k(const float* __restrict__ h, float* __restrict__ ze)
{
    extern __shared__ float s[];
    float* sh = s;          // [128 ch][129]
    float* sw = s + ZSH;    // [128 ch][65]  (WcT)

    const int tid = threadIdx.x;
    const int t0  = blockIdx.x * 128;
    const int b   = blockIdx.z;

    for (int idx = tid; idx < 128 * 128; idx += 128) {
        int ci = idx >> 7, t = idx & 127;
        sh[ci * 129 + t] = h[((size_t)b * H + ci) * T2 + t0 + t];
    }
    for (int idx = tid; idx < H * DD; idx += 128) {
        int ch = idx >> 6, dq = idx & 63;
        sw[ch * 65 + dq] = g_WcT[idx];
    }
    __syncthreads();

    const int dqslot = tid & 7;    // dq = dqslot*8 + c
    const int tslot  = tid >> 3;
    const int dq0 = dqslot * 8;

    float acc[8][8];
    #pragma unroll
    for (int c = 0; c < 8; c++) {
        float bv = g_bc[dq0 + c];
        #pragma unroll
        for (int j = 0; j < 8; j++) acc[c][j] = bv;
    }

    #pragma unroll 2
    for (int ch = 0; ch < H; ch++) {
        float xv[8], wv[8];
        #pragma unroll
        for (int j = 0; j < 8; j++) xv[j] = fmaxf(sh[ch * 129 + tslot * 8 + j], 0.f);
        #pragma unroll
        for (int c = 0; c < 8; c++) wv[c] = sw[ch * 65 + dq0 + c];
        #pragma unroll
        for (int c = 0; c < 8; c++)
            #pragma unroll
            for (int j = 0; j < 8; j++)
                acc[c][j] = fmaf(xv[j], wv[c], acc[c][j]);
    }

    #pragma unroll
    for (int j = 0; j < 8; j++) {
        size_t n = (size_t)b * T2 + t0 + tslot * 8 + j;
        float2* op = (float2*)(ze + n * DD + dq0);   // 8B-aligned region: STG.64
        op[0] = make_float2(acc[0][j], acc[1][j]);
        op[1] = make_float2(acc[2][j], acc[3][j]);
        op[2] = make_float2(acc[4][j], acc[5][j]);
        op[3] = make_float2(acc[6][j], acc[7][j]);
    }
}

// ---------------- VQ as tiled distance-GEMM: 128 n x 512 k per block ----------------
#define VSZ  (64 * 129)          // szeT [d][n]
#define VSCB (64 * 65)           // scbT [d][k-chunk]
#define VSMF (VSZ + VSCB + KCB)  // floats before int region
__global__ void __launch_bounds__(256) vqgemm_k(
    const float* __restrict__ ze, const float* __restrict__ cb,
    float* __restrict__ zq, float* __restrict__ enc, float* __restrict__ idxout)
{
    extern __shared__ float s[];
    float* szeT = s;
    float* scbT = s + VSZ;
    float* scn  = s + VSZ + VSCB;
    int*   sbk  = (int*)(s + VSMF);

    const int tid = threadIdx.x;
    const int n0  = blockIdx.x * 128;

    for (int idx = tid; idx < 128 * DD; idx += 256) {
        int n = idx >> 6, d = idx & 63;
        szeT[d * 129 + n] = ze[(size_t)(n0 + n) * DD + d];
    }
    for (int k = tid; k < KCB; k += 256) scn[k] = g_cnorm[k];
    __syncthreads();

    const int nslot = tid >> 3;    // 0..31, n = nslot*4 + i
    const int kslot = tid & 7;     // k = chunk + kslot + 8*j

    float best[4] = {3.4e38f, 3.4e38f, 3.4e38f, 3.4e38f};
    int   bk[4]   = {0, 0, 0, 0};

    for (int kc = 0; kc < KCB; kc += 64) {
        for (int idx = tid; idx < 64 * 64; idx += 256) {
            int k = idx >> 6, d = idx & 63;
            scbT[d * 65 + k] = cb[(size_t)(kc + k) * DD + d];
        }
        __syncthreads();

        float acc[4][8];
        #pragma unroll
        for (int i = 0; i < 4; i++)
            #pragma unroll
            for (int j = 0; j < 8; j++) acc[i][j] = 0.f;

        #pragma unroll 2
        for (int d = 0; d < DD; d++) {
            float fz[4], fc[8];
            #pragma unroll
            for (int i = 0; i < 4; i++) fz[i] = szeT[d * 129 + nslot * 4 + i];
            #pragma unroll
            for (int j = 0; j < 8; j++) fc[j] = scbT[d * 65 + kslot + 8 * j];
            #pragma unroll
            for (int i = 0; i < 4; i++)
                #pragma unroll
                for (int j = 0; j < 8; j++)
                    acc[i][j] = fmaf(fz[i], fc[j], acc[i][j]);
        }

        #pragma unroll
        for (int i = 0; i < 4; i++)
            #pragma unroll
            for (int j = 0; j < 8; j++) {
                int kg = kc + kslot + 8 * j;
                float dist = scn[kg] - 2.f * acc[i][j];
                if (dist < best[i]) { best[i] = dist; bk[i] = kg; }
            }
        __syncthreads();
    }

    // reduce over the 8 kslot lanes (consecutive lanes, width 8)
    #pragma unroll
    for (int off = 4; off > 0; off >>= 1) {
        #pragma unroll
        for (int i = 0; i < 4; i++) {
            float ob = __shfl_down_sync(0xffffffffu, best[i], off, 8);
            int   ok = __shfl_down_sync(0xffffffffu, bk[i],   off, 8);
            if (ob < best[i] || (ob == best[i] && ok < bk[i])) { best[i] = ob; bk[i] = ok; }
        }
    }
    if (kslot == 0)
        #pragma unroll
        for (int i = 0; i < 4; i++) sbk[nslot * 4 + i] = bk[i];
    __syncthreads();

    // epilogue: z_q gather + loss partial (scalar stores; zq base is only 4B-aligned)
    float part = 0.f;
    for (int idx = tid; idx < 128 * DD; idx += 256) {
        int nl = idx >> 6, d = idx & 63;
        int kk = sbk[nl];
        float c = cb[(size_t)kk * DD + d];
        float f = szeT[d * 129 + nl];
        zq[(size_t)(n0 + nl) * DD + d] = c;
        float df = c - f;
        part = fmaf(df, df, part);
    }
    if (tid < 128) {
        int kk = sbk[tid];
        idxout[n0 + tid] = (float)kk;
        enc[(size_t)(n0 + tid) * KCB + kk] = 1.f;
        atomicAdd(&g_hist[kk], 1);
    }

    #pragma unroll
    for (int o = 16; o > 0; o >>= 1) part += __shfl_down_sync(0xffffffffu, part, o);
    __shared__ float wsum[8];
    if ((tid & 31) == 0) wsum[tid >> 5] = part;
    __syncthreads();
    if (tid < 8) {
        float v = wsum[tid];
        #pragma unroll
        for (int o = 4; o > 0; o >>= 1) v += __shfl_down_sync(0xffu, v, o);
        if (tid == 0) atomicAdd(&g_losssum, v);
    }
}

// ---------------- finalize scalars ----------------
__global__ void fin_k(float* __restrict__ loss_out, float* __restrict__ perp_out)
{
    __shared__ float red[512];
    const int k = threadIdx.x;
    float p = (float)g_hist[k] * (1.0f / (float)NN);
    red[k] = p * logf(p + 1e-10f);
    __syncthreads();
    for (int s2 = 256; s2 > 0; s2 >>= 1) {
        if (k < s2) red[k] += red[k + s2];
        __syncthreads();
    }
    if (k == 0) {
        perp_out[0] = expf(-red[0]);
        loss_out[0] = 1.25f * g_losssum / (float)((size_t)NN * DD);
    }
}

// ---------------- launcher ----------------
extern "C" void kernel_launch(void* const* d_in, const int* in_sizes, int n_in,
                              void* d_out, int out_size)
{
    const float* x     = (const float*)d_in[0];
    const float* w1    = (const float*)d_in[1];
    const float* b1    = (const float*)d_in[2];
    const float* w2    = (const float*)d_in[3];
    const float* b2    = (const float*)d_in[4];
    const float* w3    = (const float*)d_in[5];
    const float* b3    = (const float*)d_in[6];
    const float* r0w1  = (const float*)d_in[7];
    const float* r0w2  = (const float*)d_in[8];
    const float* r1w1  = (const float*)d_in[9];
    const float* r1w2  = (const float*)d_in[10];
    const float* w_out = (const float*)d_in[11];
    const float* b_out = (const float*)d_in[12];
    const float* wpq   = (const float*)d_in[13];
    const float* bpq   = (const float*)d_in[14];
    const float* cb    = (const float*)d_in[15];

    float* outp = (float*)d_out;
    const size_t NZ = (size_t)NN * DD;
    float* o_loss = outp;
    float* o_zq   = outp + 1;
    float* o_perp = outp + 1 + NZ;
    float* o_ze   = outp + 2 + NZ;
    float* o_enc  = outp + 2 + 2 * NZ;
    float* o_idx  = outp + 2 + 2 * NZ + (size_t)NN * KCB;

    static int attr_done = 0;
    const int res_smem = (RSH + RSTA + RSW) * 4;          // 148,864
    const int z_smem   = (ZSH + ZSW) * 4;                 // 99,328
    const int vq_smem  = VSMF * 4 + 128 * 4;              // 52,736
    if (!attr_done) {
        cudaFuncSetAttribute(resblock_k, cudaFuncAttributeMaxDynamicSharedMemorySize, res_smem);
        cudaFuncSetAttribute(zfused_k,   cudaFuncAttributeMaxDynamicSharedMemorySize, z_smem);
        cudaFuncSetAttribute(vqgemm_k,   cudaFuncAttributeMaxDynamicSharedMemorySize, vq_smem);
        attr_done = 1;
    }

    precompute_k<<<1, 256>>>(wpq, w_out, b_out, bpq, cb);
    zero_enc_k<<<8192, 256>>>(o_enc);

    convS2_k<<<dim3(T1 / 128, HH / 16, BB), 128>>>(x,    w1, b1, g_h1, CIN, T0, HH, T1);
    convS2_k<<<dim3(T2 / 128, H  / 16, BB), 128>>>(g_h1, w2, b2, g_h2, HH,  T1, H,  T2);
    convS1_k<<<dim3(T2 / 128, H  / 16, BB), 128>>>(g_h2, w3, b3, g_h3, H, H);

    resblock_k<<<dim3(T2 / 128, 1, BB), 256, res_smem>>>(g_h3, r0w1, r0w2, g_h2);
    resblock_k<<<dim3(T2 / 128, 1, BB), 256, res_smem>>>(g_h2, r1w1, r1w2, g_h3);

    zfused_k<<<dim3(T2 / 128, 1, BB), 128, z_smem>>>(g_h3, o_ze);

    vqgemm_k<<<NN / 128, 256, vq_smem>>>(o_ze, cb, o_zq, o_enc, o_idx);

    fin_k<<<1, 512>>>(o_loss, o_perp);
}